// round 2
// baseline (speedup 1.0000x reference)
#include <cuda_runtime.h>

#define SQ   32
#define EMB  1024
#define NH   16
#define HD   64
#define PASTN 32768
#define TOT  32800
#define NSPLIT 33
#define CHUNK 1024

// Scratch (allocation-free rule: __device__ globals)
__device__ float g_qkv[SQ * 3 * EMB];                 // [s][3E]
__device__ float g_po [NH * NSPLIT * SQ * HD];        // partial O
__device__ float g_pml[NH * NSPLIT * SQ * 2];         // partial (m, l)
__device__ float g_a  [SQ * EMB];                     // merged heads

// ---------------------------------------------------------------------------
// Kernel 1: qkv = x @ w_attn + b_attn ; write new K/V into present tail
// grid (24, 8), block 128. Each block: 128 cols x 4 rows.
// ---------------------------------------------------------------------------
__global__ __launch_bounds__(128) void qkv_kernel(
    const float* __restrict__ x, const float* __restrict__ w,
    const float* __restrict__ b, float* __restrict__ dout)
{
    __shared__ float xs[4 * EMB];
    const int c  = blockIdx.x * 128 + threadIdx.x;   // 0..3071
    const int s0 = blockIdx.y * 4;
    for (int i = threadIdx.x; i < 4 * EMB; i += 128)
        xs[i] = x[s0 * EMB + i];
    __syncthreads();

    float a0 = 0.f, a1 = 0.f, a2 = 0.f, a3 = 0.f;
#pragma unroll 8
    for (int k = 0; k < EMB; k++) {
        float wv = w[(size_t)k * (3 * EMB) + c];
        a0 = fmaf(xs[k],           wv, a0);
        a1 = fmaf(xs[EMB + k],     wv, a1);
        a2 = fmaf(xs[2 * EMB + k], wv, a2);
        a3 = fmaf(xs[3 * EMB + k], wv, a3);
    }
    const float bv = b[c];
    float vals[4] = {a0 + bv, a1 + bv, a2 + bv, a3 + bv};

#pragma unroll
    for (int r = 0; r < 4; r++) {
        const int s = s0 + r;
        g_qkv[s * 3 * EMB + c] = vals[r];
        if (c >= EMB) {                       // K or V -> present tail
            const int which = (c >= 2 * EMB) ? 1 : 0;   // 0=K, 1=V
            const int cc = c - EMB - which * EMB;
            const int h = cc / HD, d = cc % HD;
            const size_t off = (size_t)SQ * EMB
                + ((size_t)which * NH + h) * (size_t)TOT * HD
                + (size_t)(PASTN + s) * HD + d;
            dout[off] = vals[r];
        }
    }
}

// ---------------------------------------------------------------------------
// Warp reductions
// ---------------------------------------------------------------------------
__device__ __forceinline__ float wmax(float v) {
#pragma unroll
    for (int o = 16; o; o >>= 1) v = fmaxf(v, __shfl_xor_sync(0xffffffffu, v, o));
    return v;
}
__device__ __forceinline__ float wsum(float v) {
#pragma unroll
    for (int o = 16; o; o >>= 1) v += __shfl_xor_sync(0xffffffffu, v, o);
    return v;
}

// ---------------------------------------------------------------------------
// Kernel 2: flash-decoding attention, fused KV-cache copy-through.
// grid (NSPLIT, NH), 256 threads (8 warps). Warp w owns queries j0..j0+3.
// ---------------------------------------------------------------------------
__global__ __launch_bounds__(256) void attn_kernel(
    const float* __restrict__ past, float* __restrict__ dout)
{
    const int split = blockIdx.x, h = blockIdx.y;
    const int t0   = split * CHUNK;
    const int tend = min(t0 + CHUNK, TOT);
    const int tid  = threadIdx.x, w = tid >> 5, lane = tid & 31;

    __shared__ float qs[SQ][HD];       // 8 KB
    __shared__ float Kt[HD][33];       // transposed + padded (conflict-free)
    __shared__ float Vs[32][HD];       // 8 KB
    __shared__ float Ss[SQ][32];       // probs

    for (int i = tid; i < SQ * HD; i += 256) {
        const int j = i >> 6, d = i & 63;
        qs[j][d] = g_qkv[j * 3 * EMB + h * HD + d];
    }

    float m[4], l[4];
    float2 acc[4];
#pragma unroll
    for (int r = 0; r < 4; r++) { m[r] = -1e30f; l[r] = 0.f; acc[r] = make_float2(0.f, 0.f); }

    float* presK = dout + SQ * EMB + (size_t)h * TOT * HD;
    float* presV = presK + (size_t)NH * TOT * HD;
    const bool isnew = (t0 >= PASTN);
    const float* srcK = isnew ? (presK + (size_t)t0 * HD)
                              : (past + (size_t)h * PASTN * HD + (size_t)t0 * HD);
    const float* srcV = isnew ? (presV + (size_t)t0 * HD)
                              : (past + (size_t)(NH + h) * PASTN * HD + (size_t)t0 * HD);
    const int j0 = w * 4;

    for (int tt = t0; tt < tend; tt += 32) {
        __syncthreads();
        const int base = (tt - t0) * HD;
        for (int i = tid; i < 32 * HD; i += 256) {
            const float kv = srcK[base + i];
            const float vv = srcV[base + i];
            const int kk = i >> 6, d = i & 63;
            Kt[d][kk] = kv;
            Vs[kk][d] = vv;
            if (!isnew) {                      // copy-through to present
                presK[(size_t)tt * HD + i] = kv;
                presV[(size_t)tt * HD + i] = vv;
            }
        }
        __syncthreads();

        // scores: this lane owns key kk=lane; 4 query rows
        float s0 = 0.f, s1 = 0.f, s2 = 0.f, s3 = 0.f;
#pragma unroll
        for (int d = 0; d < HD; d += 4) {
            const float k0 = Kt[d][lane],   k1 = Kt[d + 1][lane];
            const float k2 = Kt[d + 2][lane], k3 = Kt[d + 3][lane];
            const float4 q0 = *(const float4*)&qs[j0][d];
            const float4 q1 = *(const float4*)&qs[j0 + 1][d];
            const float4 q2 = *(const float4*)&qs[j0 + 2][d];
            const float4 q3 = *(const float4*)&qs[j0 + 3][d];
            s0 += q0.x * k0 + q0.y * k1 + q0.z * k2 + q0.w * k3;
            s1 += q1.x * k0 + q1.y * k1 + q1.z * k2 + q1.w * k3;
            s2 += q2.x * k0 + q2.y * k1 + q2.z * k2 + q2.w * k3;
            s3 += q3.x * k0 + q3.y * k1 + q3.z * k2 + q3.w * k3;
        }
        const float sc = 0.125f;
        s0 *= sc; s1 *= sc; s2 *= sc; s3 *= sc;
        if (tt >= PASTN) {                    // causal mask for new keys only
            const int key = tt - PASTN + lane;
            if (key > j0)     s0 = -1e30f;
            if (key > j0 + 1) s1 = -1e30f;
            if (key > j0 + 2) s2 = -1e30f;
            if (key > j0 + 3) s3 = -1e30f;
        }

        float srow[4] = {s0, s1, s2, s3};
#pragma unroll
        for (int r = 0; r < 4; r++) {
            const float tm = wmax(srow[r]);
            const float nm = fmaxf(m[r], tm);
            const float al = __expf(m[r] - nm);
            const float p  = __expf(srow[r] - nm);
            const float rs = wsum(p);
            l[r] = l[r] * al + rs;
            m[r] = nm;
            acc[r].x *= al; acc[r].y *= al;
            Ss[j0 + r][lane] = p;
        }
        __syncwarp();

#pragma unroll 4
        for (int kk = 0; kk < 32; kk++) {
            const float2 v = *(const float2*)&Vs[kk][lane * 2];
            const float p0 = Ss[j0][kk],     p1 = Ss[j0 + 1][kk];
            const float p2 = Ss[j0 + 2][kk], p3 = Ss[j0 + 3][kk];
            acc[0].x = fmaf(p0, v.x, acc[0].x); acc[0].y = fmaf(p0, v.y, acc[0].y);
            acc[1].x = fmaf(p1, v.x, acc[1].x); acc[1].y = fmaf(p1, v.y, acc[1].y);
            acc[2].x = fmaf(p2, v.x, acc[2].x); acc[2].y = fmaf(p2, v.y, acc[2].y);
            acc[3].x = fmaf(p3, v.x, acc[3].x); acc[3].y = fmaf(p3, v.y, acc[3].y);
        }
    }

    const int pb = (h * NSPLIT + split) * SQ;
#pragma unroll
    for (int r = 0; r < 4; r++) {
        const int j = j0 + r;
        g_po[(size_t)(pb + j) * HD + lane * 2]     = acc[r].x;
        g_po[(size_t)(pb + j) * HD + lane * 2 + 1] = acc[r].y;
        if (lane == 0) {
            g_pml[(pb + j) * 2]     = m[r];
            g_pml[(pb + j) * 2 + 1] = l[r];
        }
    }
}

// ---------------------------------------------------------------------------
// Kernel 3: combine split partials (LSE merge), merge heads into g_a
// grid (NH, SQ), block HD
// ---------------------------------------------------------------------------
__global__ __launch_bounds__(HD) void combine_kernel()
{
    const int h = blockIdx.x, j = blockIdx.y, d = threadIdx.x;
    float gm = -1e30f;
    for (int sp = 0; sp < NSPLIT; sp++)
        gm = fmaxf(gm, g_pml[((h * NSPLIT + sp) * SQ + j) * 2]);
    float L = 0.f, o = 0.f;
    for (int sp = 0; sp < NSPLIT; sp++) {
        const int idx = (h * NSPLIT + sp) * SQ + j;
        const float f = __expf(g_pml[idx * 2] - gm);
        L += g_pml[idx * 2 + 1] * f;
        o += f * g_po[(size_t)idx * HD + d];
    }
    g_a[j * EMB + h * HD + d] = o / L;
}

// ---------------------------------------------------------------------------
// Kernel 4: out = g_a @ w_proj + b_proj   -> d_out[0 : 32*1024)
// grid (8, 8), block 128
// ---------------------------------------------------------------------------
__global__ __launch_bounds__(128) void proj_kernel(
    const float* __restrict__ w, const float* __restrict__ b,
    float* __restrict__ dout)
{
    __shared__ float as[4 * EMB];
    const int c  = blockIdx.x * 128 + threadIdx.x;   // 0..1023
    const int s0 = blockIdx.y * 4;
    for (int i = threadIdx.x; i < 4 * EMB; i += 128)
        as[i] = g_a[s0 * EMB + i];
    __syncthreads();

    float a0 = 0.f, a1 = 0.f, a2 = 0.f, a3 = 0.f;
#pragma unroll 8
    for (int k = 0; k < EMB; k++) {
        const float wv = w[(size_t)k * EMB + c];
        a0 = fmaf(as[k],           wv, a0);
        a1 = fmaf(as[EMB + k],     wv, a1);
        a2 = fmaf(as[2 * EMB + k], wv, a2);
        a3 = fmaf(as[3 * EMB + k], wv, a3);
    }
    const float bv = b[c];
    dout[(s0 + 0) * EMB + c] = a0 + bv;
    dout[(s0 + 1) * EMB + c] = a1 + bv;
    dout[(s0 + 2) * EMB + c] = a2 + bv;
    dout[(s0 + 3) * EMB + c] = a3 + bv;
}

// ---------------------------------------------------------------------------
extern "C" void kernel_launch(void* const* d_in, const int* in_sizes, int n_in,
                              void* d_out, int out_size)
{
    const float* x      = (const float*)d_in[0];
    const float* past   = (const float*)d_in[1];
    const float* w_attn = (const float*)d_in[2];
    const float* b_attn = (const float*)d_in[3];
    const float* w_proj = (const float*)d_in[4];
    const float* b_proj = (const float*)d_in[5];
    float* out = (float*)d_out;

    qkv_kernel   <<<dim3(24, 8),        128>>>(x, w_attn, b_attn, out);
    attn_kernel  <<<dim3(NSPLIT, NH),   256>>>(past, out);
    combine_kernel<<<dim3(NH, SQ),       HD>>>();
    proj_kernel  <<<dim3(8, 8),         128>>>(w_proj, b_proj, out);
}

// round 3
// speedup vs baseline: 1.2469x; 1.2469x over previous
#include <cuda_runtime.h>

#define SQ     32
#define EMB    1024
#define NH     16
#define HD     64
#define PASTN  32768
#define TOT    32800
#define NSPLIT 33
#define CHUNK  1024
#define KCH    8
#define KCHLEN 128

// Scratch (allocation-free rule: __device__ globals)
__device__ float g_qkv [SQ * 3 * EMB];                // [s][3E]
__device__ float g_po  [NH * NSPLIT * SQ * HD];       // partial O
__device__ float g_pml [NH * NSPLIT * SQ * 2];        // partial (m, l)
__device__ float g_a   [SQ * EMB];                    // merged heads
__device__ float g_pqkv[KCH * SQ * 3 * EMB];          // split-K partials (qkv)
__device__ float g_pprj[KCH * SQ * EMB];              // split-K partials (proj)

// ------------------------- packed f32x2 helpers ----------------------------
__device__ __forceinline__ unsigned long long ffma2(
    unsigned long long a, unsigned long long b, unsigned long long c) {
    unsigned long long d;
    asm("fma.rn.f32x2 %0, %1, %2, %3;" : "=l"(d) : "l"(a), "l"(b), "l"(c));
    return d;
}
__device__ __forceinline__ unsigned long long mul2(
    unsigned long long a, unsigned long long b) {
    unsigned long long d;
    asm("mul.rn.f32x2 %0, %1, %2;" : "=l"(d) : "l"(a), "l"(b));
    return d;
}
__device__ __forceinline__ unsigned long long pack2(float x, float y) {
    unsigned long long r;
    asm("mov.b64 %0, {%1, %2};" : "=l"(r) : "f"(x), "f"(y));
    return r;
}
__device__ __forceinline__ float2 unpack2(unsigned long long v) {
    float2 r;
    asm("mov.b64 {%0, %1}, %2;" : "=f"(r.x), "=f"(r.y) : "l"(v));
    return r;
}

// ---------------------------------------------------------------------------
// Split-K GEMM partial: part[kc][r][C] = x[r][k0:k0+128] @ w[k0:k0+128][C]
// grid (C/128, KCH), block 128
// ---------------------------------------------------------------------------
__global__ __launch_bounds__(128) void gemm_part_kernel(
    const float* __restrict__ xsrc, const float* __restrict__ w,
    float* __restrict__ part, int C)
{
    __shared__ float xs_t[KCHLEN][36];   // transposed, padded (float4-aligned)
    const int c  = blockIdx.x * 128 + threadIdx.x;
    const int k0 = blockIdx.y * KCHLEN;

#pragma unroll 4
    for (int j = 0; j < SQ; j++)
        xs_t[threadIdx.x][j] = xsrc[j * EMB + k0 + threadIdx.x];
    __syncthreads();

    unsigned long long acc[16];
#pragma unroll
    for (int i = 0; i < 16; i++) acc[i] = 0ull;

#pragma unroll 16
    for (int k = 0; k < KCHLEN; k++) {
        const float wv = w[(size_t)(k0 + k) * C + c];
        const unsigned long long w2 = pack2(wv, wv);
#pragma unroll
        for (int r4 = 0; r4 < 8; r4++) {
            const ulonglong2 x4 = *(const ulonglong2*)&xs_t[k][r4 * 4];
            acc[r4 * 2]     = ffma2(x4.x, w2, acc[r4 * 2]);
            acc[r4 * 2 + 1] = ffma2(x4.y, w2, acc[r4 * 2 + 1]);
        }
    }

    float* p = part + (size_t)blockIdx.y * SQ * C + c;
#pragma unroll
    for (int i = 0; i < 16; i++) {
        const float2 v = unpack2(acc[i]);
        p[(size_t)(2 * i)     * C] = v.x;
        p[(size_t)(2 * i + 1) * C] = v.y;
    }
}

// ---------------------------------------------------------------------------
// Reduce qkv partials + bias -> g_qkv ; scatter new K/V rows into present tail
// grid (12, 32), block 256
// ---------------------------------------------------------------------------
__global__ __launch_bounds__(256) void reduce_qkv_kernel(
    const float* __restrict__ b, float* __restrict__ dout)
{
    const int c = blockIdx.x * 256 + threadIdx.x;   // 0..3071
    const int r = blockIdx.y;
    float v = b[c];
#pragma unroll
    for (int kc = 0; kc < KCH; kc++)
        v += g_pqkv[((size_t)kc * SQ + r) * (3 * EMB) + c];
    g_qkv[r * 3 * EMB + c] = v;
    if (c >= EMB) {
        const int which = (c >= 2 * EMB) ? 1 : 0;   // 0=K, 1=V
        const int cc = c - EMB - which * EMB;
        const int h = cc / HD, d = cc % HD;
        dout[(size_t)SQ * EMB
             + ((size_t)which * NH + h) * (size_t)TOT * HD
             + (size_t)(PASTN + r) * HD + d] = v;
    }
}

// ---------------------------------------------------------------------------
// Warp reductions
// ---------------------------------------------------------------------------
__device__ __forceinline__ float wmax(float v) {
#pragma unroll
    for (int o = 16; o; o >>= 1) v = fmaxf(v, __shfl_xor_sync(0xffffffffu, v, o));
    return v;
}
__device__ __forceinline__ float wsum(float v) {
#pragma unroll
    for (int o = 16; o; o >>= 1) v += __shfl_xor_sync(0xffffffffu, v, o);
    return v;
}

// ---------------------------------------------------------------------------
// Flash-decoding attention with fused KV copy-through, FFMA2 inner loops.
// grid (NSPLIT, NH), 256 threads (8 warps), warp owns 4 query rows.
// ---------------------------------------------------------------------------
__global__ __launch_bounds__(256) void attn_kernel(
    const float* __restrict__ past, float* __restrict__ dout)
{
    const int split = blockIdx.x, h = blockIdx.y;
    const int t0   = split * CHUNK;
    const int tend = min(t0 + CHUNK, TOT);
    const int tid  = threadIdx.x, w = tid >> 5, lane = tid & 31;
    const int j0 = w * 4;

    __shared__ float  qs_t[HD][36];    // q transposed [d][j], padded
    __shared__ float2 Kt2 [HD][33];    // K transposed, duplicated (k,k)
    __shared__ float  Vs  [32][HD];    // V row-major
    __shared__ float  Ss2 [SQ][64];    // probs duplicated (p,p)

    for (int i = tid; i < SQ * HD; i += 256) {
        const int d = i & 63, j = i >> 6;
        qs_t[d][j] = g_qkv[j * 3 * EMB + h * HD + d];
    }

    unsigned long long acc[4] = {0ull, 0ull, 0ull, 0ull};
    float m[4], l[4];
#pragma unroll
    for (int r = 0; r < 4; r++) { m[r] = -1e30f; l[r] = 0.f; }

    float* presK = dout + SQ * EMB + (size_t)h * TOT * HD;
    float* presV = presK + (size_t)NH * TOT * HD;
    const bool isnew = (t0 >= PASTN);
    const float* srcK = isnew ? (presK + (size_t)t0 * HD)
                              : (past + (size_t)h * PASTN * HD + (size_t)t0 * HD);
    const float* srcV = isnew ? (presV + (size_t)t0 * HD)
                              : (past + (size_t)(NH + h) * PASTN * HD + (size_t)t0 * HD);

    for (int tt = t0; tt < tend; tt += 32) {
        __syncthreads();
        const int base = (tt - t0) * HD;
        // 512 float4 groups: per thread 2
#pragma unroll
        for (int i4 = tid; i4 < 512; i4 += 256) {
            const int kk = i4 >> 4, d4 = (i4 & 15) << 2;
            const float4 kv = *(const float4*)&srcK[base + kk * HD + d4];
            const float4 vv = *(const float4*)&srcV[base + kk * HD + d4];
            Kt2[d4    ][kk] = make_float2(kv.x, kv.x);
            Kt2[d4 + 1][kk] = make_float2(kv.y, kv.y);
            Kt2[d4 + 2][kk] = make_float2(kv.z, kv.z);
            Kt2[d4 + 3][kk] = make_float2(kv.w, kv.w);
            *(float4*)&Vs[kk][d4] = vv;
            if (!isnew) {
                *(float4*)&presK[(size_t)tt * HD + kk * HD + d4] = kv;
                *(float4*)&presV[(size_t)tt * HD + kk * HD + d4] = vv;
            }
        }
        __syncthreads();

        // ---- scores: lane owns key kk=lane, 4 queries packed in 2 f32x2 ----
        unsigned long long s01 = 0ull, s23 = 0ull;
#pragma unroll
        for (int d = 0; d < HD; d++) {
            const unsigned long long k2 = *(const unsigned long long*)&Kt2[d][lane];
            const ulonglong2 q2 = *(const ulonglong2*)&qs_t[d][j0];
            s01 = ffma2(q2.x, k2, s01);
            s23 = ffma2(q2.y, k2, s23);
        }
        const float2 sa = unpack2(s01), sb = unpack2(s23);
        float sr[4] = {sa.x * 0.125f, sa.y * 0.125f, sb.x * 0.125f, sb.y * 0.125f};
        if (tt >= PASTN) {
            const int key = tt - PASTN + lane;
#pragma unroll
            for (int r = 0; r < 4; r++)
                if (key > j0 + r) sr[r] = -1e30f;
        }

#pragma unroll
        for (int r = 0; r < 4; r++) {
            const float tm = wmax(sr[r]);
            const float nm = fmaxf(m[r], tm);
            const float al = __expf(m[r] - nm);
            const float p  = __expf(sr[r] - nm);
            l[r] = l[r] * al + wsum(p);
            m[r] = nm;
            acc[r] = mul2(acc[r], pack2(al, al));
            *(unsigned long long*)&Ss2[j0 + r][2 * lane] = pack2(p, p);
        }
        __syncwarp();

        // ---- PV: lane owns dims (2*lane, 2*lane+1) ----
#pragma unroll 8
        for (int kk = 0; kk < 32; kk++) {
            const unsigned long long v2 =
                *(const unsigned long long*)&Vs[kk][lane * 2];
            acc[0] = ffma2(*(const unsigned long long*)&Ss2[j0    ][2 * kk], v2, acc[0]);
            acc[1] = ffma2(*(const unsigned long long*)&Ss2[j0 + 1][2 * kk], v2, acc[1]);
            acc[2] = ffma2(*(const unsigned long long*)&Ss2[j0 + 2][2 * kk], v2, acc[2]);
            acc[3] = ffma2(*(const unsigned long long*)&Ss2[j0 + 3][2 * kk], v2, acc[3]);
        }
    }

    const int pb = (h * NSPLIT + split) * SQ;
#pragma unroll
    for (int r = 0; r < 4; r++) {
        const int j = j0 + r;
        const float2 o = unpack2(acc[r]);
        g_po[(size_t)(pb + j) * HD + lane * 2]     = o.x;
        g_po[(size_t)(pb + j) * HD + lane * 2 + 1] = o.y;
        if (lane == 0) {
            g_pml[(pb + j) * 2]     = m[r];
            g_pml[(pb + j) * 2 + 1] = l[r];
        }
    }
}

// ---------------------------------------------------------------------------
// Combine split partials (LSE merge), merge heads -> g_a. grid (NH, SQ), HD thr
// ---------------------------------------------------------------------------
__global__ __launch_bounds__(HD) void combine_kernel()
{
    const int h = blockIdx.x, j = blockIdx.y, d = threadIdx.x;
    float gm = -1e30f;
#pragma unroll
    for (int sp = 0; sp < NSPLIT; sp++)
        gm = fmaxf(gm, g_pml[((h * NSPLIT + sp) * SQ + j) * 2]);
    float L = 0.f, o = 0.f;
#pragma unroll 4
    for (int sp = 0; sp < NSPLIT; sp++) {
        const int idx = (h * NSPLIT + sp) * SQ + j;
        const float f = __expf(g_pml[idx * 2] - gm);
        L += g_pml[idx * 2 + 1] * f;
        o = fmaf(f, g_po[(size_t)idx * HD + d], o);
    }
    g_a[j * EMB + h * HD + d] = o / L;
}

// ---------------------------------------------------------------------------
// Reduce proj partials + bias -> d_out[0 : 32*1024). grid (4, 32), block 256
// ---------------------------------------------------------------------------
__global__ __launch_bounds__(256) void reduce_proj_kernel(
    const float* __restrict__ b, float* __restrict__ dout)
{
    const int c = blockIdx.x * 256 + threadIdx.x;   // 0..1023
    const int r = blockIdx.y;
    float v = b[c];
#pragma unroll
    for (int kc = 0; kc < KCH; kc++)
        v += g_pprj[((size_t)kc * SQ + r) * EMB + c];
    dout[r * EMB + c] = v;
}

// ---------------------------------------------------------------------------
extern "C" void kernel_launch(void* const* d_in, const int* in_sizes, int n_in,
                              void* d_out, int out_size)
{
    const float* x      = (const float*)d_in[0];
    const float* past   = (const float*)d_in[1];
    const float* w_attn = (const float*)d_in[2];
    const float* b_attn = (const float*)d_in[3];
    const float* w_proj = (const float*)d_in[4];
    const float* b_proj = (const float*)d_in[5];
    float* out = (float*)d_out;

    float* pqkv; cudaGetSymbolAddress((void**)&pqkv, g_pqkv);
    float* pprj; cudaGetSymbolAddress((void**)&pprj, g_pprj);
    float* ga;   cudaGetSymbolAddress((void**)&ga,   g_a);

    gemm_part_kernel  <<<dim3(24, KCH), 128>>>(x, w_attn, pqkv, 3 * EMB);
    reduce_qkv_kernel <<<dim3(12, SQ),  256>>>(b_attn, out);
    attn_kernel       <<<dim3(NSPLIT, NH), 256>>>(past, out);
    combine_kernel    <<<dim3(NH, SQ),   HD>>>();
    gemm_part_kernel  <<<dim3(8, KCH),  128>>>(ga, w_proj, pprj, EMB);
    reduce_proj_kernel<<<dim3(4, SQ),   256>>>(b_proj, out);
}

// round 4
// speedup vs baseline: 2.0762x; 1.6651x over previous
#include <cuda_runtime.h>

#define SQ      32
#define EMB     1024
#define NH      16
#define HD      64
#define PASTN   32768
#define TOT     32800
#define PCHUNK  224
#define NSPLITS 148      // 147 past splits (224 keys, last short) + 1 new-token split
#define KCH     8
#define KCHLEN  128

// Scratch (allocation-free rule: __device__ globals)
__device__ float g_qkv [SQ * 3 * EMB];
__device__ float g_po  [NH * NSPLITS * SQ * HD];
__device__ float g_pml [NH * NSPLITS * SQ * 2];
__device__ float g_a   [SQ * EMB];
__device__ float g_pqkv[KCH * SQ * 3 * EMB];
__device__ float g_pprj[KCH * SQ * EMB];

// ------------------------- packed f32x2 helpers ----------------------------
__device__ __forceinline__ unsigned long long ffma2(
    unsigned long long a, unsigned long long b, unsigned long long c) {
    unsigned long long d;
    asm("fma.rn.f32x2 %0, %1, %2, %3;" : "=l"(d) : "l"(a), "l"(b), "l"(c));
    return d;
}
__device__ __forceinline__ unsigned long long mul2(
    unsigned long long a, unsigned long long b) {
    unsigned long long d;
    asm("mul.rn.f32x2 %0, %1, %2;" : "=l"(d) : "l"(a), "l"(b));
    return d;
}
__device__ __forceinline__ unsigned long long pack2(float x, float y) {
    unsigned long long r;
    asm("mov.b64 %0, {%1, %2};" : "=l"(r) : "f"(x), "f"(y));
    return r;
}
__device__ __forceinline__ float2 unpack2(unsigned long long v) {
    float2 r;
    asm("mov.b64 {%0, %1}, %2;" : "=f"(r.x), "=f"(r.y) : "l"(v));
    return r;
}
__device__ __forceinline__ float ex2(float x) {
    float r;
    asm("ex2.approx.f32 %0, %1;" : "=f"(r) : "f"(x));
    return r;
}

// ---------------------------------------------------------------------------
// Split-K GEMM partial: part[kc][r][C] = x[r][k0:k0+128] @ w[k0:k0+128][C]
// ---------------------------------------------------------------------------
__global__ __launch_bounds__(128) void gemm_part_kernel(
    const float* __restrict__ xsrc, const float* __restrict__ w,
    float* __restrict__ part, int C)
{
    __shared__ float xs_t[KCHLEN][36];
    const int c  = blockIdx.x * 128 + threadIdx.x;
    const int k0 = blockIdx.y * KCHLEN;

#pragma unroll 4
    for (int j = 0; j < SQ; j++)
        xs_t[threadIdx.x][j] = xsrc[j * EMB + k0 + threadIdx.x];
    __syncthreads();

    unsigned long long acc[16];
#pragma unroll
    for (int i = 0; i < 16; i++) acc[i] = 0ull;

#pragma unroll 16
    for (int k = 0; k < KCHLEN; k++) {
        const float wv = w[(size_t)(k0 + k) * C + c];
        const unsigned long long w2 = pack2(wv, wv);
#pragma unroll
        for (int r4 = 0; r4 < 8; r4++) {
            const ulonglong2 x4 = *(const ulonglong2*)&xs_t[k][r4 * 4];
            acc[r4 * 2]     = ffma2(x4.x, w2, acc[r4 * 2]);
            acc[r4 * 2 + 1] = ffma2(x4.y, w2, acc[r4 * 2 + 1]);
        }
    }

    float* p = part + (size_t)blockIdx.y * SQ * C + c;
#pragma unroll
    for (int i = 0; i < 16; i++) {
        const float2 v = unpack2(acc[i]);
        p[(size_t)(2 * i)     * C] = v.x;
        p[(size_t)(2 * i + 1) * C] = v.y;
    }
}

// ---------------------------------------------------------------------------
// Reduce qkv partials + bias -> g_qkv ; scatter new K/V rows into present tail
// ---------------------------------------------------------------------------
__global__ __launch_bounds__(256) void reduce_qkv_kernel(
    const float* __restrict__ b, float* __restrict__ dout)
{
    const int c = blockIdx.x * 256 + threadIdx.x;   // 0..3071
    const int r = blockIdx.y;
    float v = b[c];
#pragma unroll
    for (int kc = 0; kc < KCH; kc++)
        v += g_pqkv[((size_t)kc * SQ + r) * (3 * EMB) + c];
    g_qkv[r * 3 * EMB + c] = v;
    if (c >= EMB) {
        const int which = (c >= 2 * EMB) ? 1 : 0;   // 0=K, 1=V
        const int cc = c - EMB - which * EMB;
        const int h = cc / HD, d = cc % HD;
        dout[(size_t)SQ * EMB
             + ((size_t)which * NH + h) * (size_t)TOT * HD
             + (size_t)(PASTN + r) * HD + d] = v;
    }
}

// ---------------------------------------------------------------------------
// Attention: lane = query row, warp = one (head, split). No shfl, no barriers.
// grid (NSPLITS, 4), 128 threads (4 warps); warp w handles head bIdx.y*4+w.
// ---------------------------------------------------------------------------
__global__ __launch_bounds__(128, 2) void attn_kernel(
    const float* __restrict__ past, float* __restrict__ dout)
{
    const int wid = threadIdx.x >> 5, lane = threadIdx.x & 31;
    const int sp = blockIdx.x;
    const int h  = blockIdx.y * 4 + wid;

    __shared__ float Ks[4][16][HD];
    __shared__ float Vs[4][16][HD];
    float (*K)[HD] = Ks[wid];
    float (*V)[HD] = Vs[wid];

    const bool isnew = (sp == NSPLITS - 1);
    int t0, tend;
    if (isnew) { t0 = PASTN; tend = TOT; }
    else       { t0 = sp * PCHUNK; tend = min(t0 + PCHUNK, PASTN); }

    // q for row `lane`, pre-scaled by 1/sqrt(d) * log2(e)
    const float qc = 0.125f * 1.4426950408889634f;
    unsigned long long q2[32];
    {
        const float* qp = g_qkv + lane * 3 * EMB + h * HD;
#pragma unroll
        for (int i = 0; i < 16; i++) {
            const float4 v = *(const float4*)(qp + i * 4);
            q2[2 * i]     = pack2(v.x * qc, v.y * qc);
            q2[2 * i + 1] = pack2(v.z * qc, v.w * qc);
        }
    }

    unsigned long long o2[32];
#pragma unroll
    for (int i = 0; i < 32; i++) o2[i] = 0ull;
    float m = -1e30f, l = 0.f;

    float* presK = dout + SQ * EMB + (size_t)h * TOT * HD;
    float* presV = presK + (size_t)NH * TOT * HD;
    const float* srcK = isnew ? (presK + (size_t)t0 * HD)
                              : (past + ((size_t)h * PASTN + t0) * (size_t)HD);
    const float* srcV = isnew ? (presV + (size_t)t0 * HD)
                              : (past + ((size_t)(NH + h) * PASTN + t0) * (size_t)HD);

    for (int tt = t0; tt < tend; tt += 16) {
        const size_t base = (size_t)(tt - t0) * HD;
        __syncwarp();
        // 16 keys x 64 floats = 256 float4 for K and for V; 8 per lane each
#pragma unroll
        for (int r = 0; r < 8; r++) {
            const int f4 = r * 32 + lane;                // 0..255
            const int kk = f4 >> 4, dd = (f4 & 15) << 2;
            const float4 kv = *(const float4*)&srcK[base + (size_t)f4 * 4];
            const float4 vv = *(const float4*)&srcV[base + (size_t)f4 * 4];
            *(float4*)&K[kk][dd] = kv;
            *(float4*)&V[kk][dd] = vv;
            if (!isnew) {
                *(float4*)&presK[(size_t)tt * HD + (size_t)f4 * 4] = kv;
                *(float4*)&presV[(size_t)tt * HD + (size_t)f4 * 4] = vv;
            }
        }
        __syncwarp();

        // ---- scores for 16 keys (all via broadcast LDS) ----
        float s[16];
#pragma unroll
        for (int kk = 0; kk < 16; kk++) {
            unsigned long long a0 = 0ull, a1 = 0ull;
#pragma unroll
            for (int ii = 0; ii < 16; ii++) {
                const ulonglong2 k2 = *(const ulonglong2*)&K[kk][ii * 4];
                a0 = ffma2(q2[2 * ii],     k2.x, a0);
                a1 = ffma2(q2[2 * ii + 1], k2.y, a1);
            }
            const float2 fa = unpack2(a0), fb = unpack2(a1);
            s[kk] = (fa.x + fa.y) + (fb.x + fb.y);
            if (isnew) {
                if (tt - PASTN + kk > lane) s[kk] = -1e30f;
            }
        }

        // ---- online softmax update (register trees, all 32 rows at once) ----
        float tm = s[0];
#pragma unroll
        for (int kk = 1; kk < 16; kk++) tm = fmaxf(tm, s[kk]);
        const float nm = fmaxf(m, tm);
        const float al = ex2(m - nm);
        m = nm;
        float ps = 0.f;
#pragma unroll
        for (int kk = 0; kk < 16; kk++) {
            s[kk] = ex2(s[kk] - nm);
            ps += s[kk];
        }
        l = l * al + ps;
        const unsigned long long al2 = pack2(al, al);
#pragma unroll
        for (int i = 0; i < 32; i++) o2[i] = mul2(o2[i], al2);

        // ---- PV accumulate ----
#pragma unroll
        for (int kk = 0; kk < 16; kk++) {
            const unsigned long long p2 = pack2(s[kk], s[kk]);
#pragma unroll
            for (int ii = 0; ii < 16; ii++) {
                const ulonglong2 v2 = *(const ulonglong2*)&V[kk][ii * 4];
                o2[2 * ii]     = ffma2(p2, v2.x, o2[2 * ii]);
                o2[2 * ii + 1] = ffma2(p2, v2.y, o2[2 * ii + 1]);
            }
        }
    }

    // ---- epilogue: per-lane partial (m, l, o) ----
    const int pb = (h * NSPLITS + sp) * SQ + lane;
    float* pop = g_po + (size_t)pb * HD;
#pragma unroll
    for (int i = 0; i < 16; i++) {
        const float2 a = unpack2(o2[2 * i]);
        const float2 b = unpack2(o2[2 * i + 1]);
        float4 v; v.x = a.x; v.y = a.y; v.z = b.x; v.w = b.y;
        *(float4*)&pop[i * 4] = v;
    }
    g_pml[pb * 2]     = m;
    g_pml[pb * 2 + 1] = l;
}

// ---------------------------------------------------------------------------
// Combine split partials (LSE merge in log2 domain) -> g_a. grid (NH,SQ), 64 thr
// ---------------------------------------------------------------------------
__global__ __launch_bounds__(HD) void combine_kernel()
{
    const int h = blockIdx.x, j = blockIdx.y, d = threadIdx.x;
    __shared__ float sm[NSPLITS], sf[NSPLITS];

    for (int i = d; i < NSPLITS; i += HD)
        sm[i] = g_pml[((h * NSPLITS + i) * SQ + j) * 2];
    __syncthreads();

    float g0 = -1e30f, g1 = -1e30f, g2 = -1e30f, g3 = -1e30f;
#pragma unroll 4
    for (int i = 0; i < NSPLITS; i += 4) {
        g0 = fmaxf(g0, sm[i]);     g1 = fmaxf(g1, sm[i + 1]);
        g2 = fmaxf(g2, sm[i + 2]); g3 = fmaxf(g3, sm[i + 3]);
    }
    const float gm = fmaxf(fmaxf(g0, g1), fmaxf(g2, g3));
    __syncthreads();
    for (int i = d; i < NSPLITS; i += HD)
        sf[i] = ex2(sm[i] - gm);
    __syncthreads();

    float L0 = 0.f, L1 = 0.f;
#pragma unroll 4
    for (int i = 0; i < NSPLITS; i += 2) {
        L0 = fmaf(g_pml[((h * NSPLITS + i) * SQ + j) * 2 + 1],     sf[i],     L0);
        L1 = fmaf(g_pml[((h * NSPLITS + i + 1) * SQ + j) * 2 + 1], sf[i + 1], L1);
    }
    const float L = L0 + L1;

    float o0 = 0.f, o1 = 0.f, o2 = 0.f, o3 = 0.f;
    const float* po = g_po + ((size_t)(h * NSPLITS) * SQ + j) * HD + d;
#pragma unroll 4
    for (int i = 0; i < NSPLITS; i += 4) {
        o0 = fmaf(sf[i],     po[(size_t)(i)     * SQ * HD], o0);
        o1 = fmaf(sf[i + 1], po[(size_t)(i + 1) * SQ * HD], o1);
        o2 = fmaf(sf[i + 2], po[(size_t)(i + 2) * SQ * HD], o2);
        o3 = fmaf(sf[i + 3], po[(size_t)(i + 3) * SQ * HD], o3);
    }
    g_a[j * EMB + h * HD + d] = ((o0 + o1) + (o2 + o3)) / L;
}

// ---------------------------------------------------------------------------
// Reduce proj partials + bias -> d_out[0 : 32*1024)
// ---------------------------------------------------------------------------
__global__ __launch_bounds__(256) void reduce_proj_kernel(
    const float* __restrict__ b, float* __restrict__ dout)
{
    const int c = blockIdx.x * 256 + threadIdx.x;   // 0..1023
    const int r = blockIdx.y;
    float v = b[c];
#pragma unroll
    for (int kc = 0; kc < KCH; kc++)
        v += g_pprj[((size_t)kc * SQ + r) * EMB + c];
    dout[r * EMB + c] = v;
}

// ---------------------------------------------------------------------------
extern "C" void kernel_launch(void* const* d_in, const int* in_sizes, int n_in,
                              void* d_out, int out_size)
{
    const float* x      = (const float*)d_in[0];
    const float* past   = (const float*)d_in[1];
    const float* w_attn = (const float*)d_in[2];
    const float* b_attn = (const float*)d_in[3];
    const float* w_proj = (const float*)d_in[4];
    const float* b_proj = (const float*)d_in[5];
    float* out = (float*)d_out;

    float* pqkv; cudaGetSymbolAddress((void**)&pqkv, g_pqkv);
    float* pprj; cudaGetSymbolAddress((void**)&pprj, g_pprj);
    float* ga;   cudaGetSymbolAddress((void**)&ga,   g_a);

    gemm_part_kernel  <<<dim3(24, KCH), 128>>>(x, w_attn, pqkv, 3 * EMB);
    reduce_qkv_kernel <<<dim3(12, SQ),  256>>>(b_attn, out);
    attn_kernel       <<<dim3(NSPLITS, 4), 128>>>(past, out);
    combine_kernel    <<<dim3(NH, SQ),   HD>>>();
    gemm_part_kernel  <<<dim3(8, KCH),  128>>>(ga, w_proj, pprj, EMB);
    reduce_proj_kernel<<<dim3(4, SQ),   256>>>(b_proj, out);
}

// round 5
// speedup vs baseline: 2.2320x; 1.0750x over previous
#include <cuda_runtime.h>

#define SQ      32
#define EMB     1024
#define NH      16
#define HD      64
#define PASTN   32768
#define TOT     32800
#define PCHUNK  224
#define NSPLITS 148      // 147 past splits + 1 new-token split
#define KCH     8
#define KCHLEN  128

// Scratch (allocation-free rule: __device__ globals)
__device__ float g_qkv [SQ * 3 * EMB];
__device__ float g_po  [NH * NSPLITS * SQ * HD];
__device__ float g_pml [NH * NSPLITS * SQ * 2];
__device__ float g_a   [SQ * EMB];
__device__ float g_pqkv[KCH * SQ * 3 * EMB];
__device__ float g_pprj[KCH * SQ * EMB];

// ------------------------- packed f32x2 helpers ----------------------------
__device__ __forceinline__ unsigned long long ffma2(
    unsigned long long a, unsigned long long b, unsigned long long c) {
    unsigned long long d;
    asm("fma.rn.f32x2 %0, %1, %2, %3;" : "=l"(d) : "l"(a), "l"(b), "l"(c));
    return d;
}
__device__ __forceinline__ unsigned long long mul2(
    unsigned long long a, unsigned long long b) {
    unsigned long long d;
    asm("mul.rn.f32x2 %0, %1, %2;" : "=l"(d) : "l"(a), "l"(b));
    return d;
}
__device__ __forceinline__ unsigned long long pack2(float x, float y) {
    unsigned long long r;
    asm("mov.b64 %0, {%1, %2};" : "=l"(r) : "f"(x), "f"(y));
    return r;
}
__device__ __forceinline__ float2 unpack2(unsigned long long v) {
    float2 r;
    asm("mov.b64 {%0, %1}, %2;" : "=f"(r.x), "=f"(r.y) : "l"(v));
    return r;
}
__device__ __forceinline__ float ex2(float x) {
    float r;
    asm("ex2.approx.f32 %0, %1;" : "=f"(r) : "f"(x));
    return r;
}
__device__ __forceinline__ void cp16(unsigned int saddr, const void* gptr) {
    asm volatile("cp.async.cg.shared.global [%0], [%1], 16;"
                 :: "r"(saddr), "l"(gptr));
}

// ---------------------------------------------------------------------------
// Split-K GEMM partial: part[kc][r][C] = x[r][k0:k0+128] @ w[k0:k0+128][C]
// ---------------------------------------------------------------------------
__global__ __launch_bounds__(128) void gemm_part_kernel(
    const float* __restrict__ xsrc, const float* __restrict__ w,
    float* __restrict__ part, int C)
{
    __shared__ float xs_t[KCHLEN][36];
    const int c  = blockIdx.x * 128 + threadIdx.x;
    const int k0 = blockIdx.y * KCHLEN;

#pragma unroll 4
    for (int j = 0; j < SQ; j++)
        xs_t[threadIdx.x][j] = xsrc[j * EMB + k0 + threadIdx.x];
    __syncthreads();

    unsigned long long acc[16];
#pragma unroll
    for (int i = 0; i < 16; i++) acc[i] = 0ull;

#pragma unroll 16
    for (int k = 0; k < KCHLEN; k++) {
        const float wv = w[(size_t)(k0 + k) * C + c];
        const unsigned long long w2 = pack2(wv, wv);
#pragma unroll
        for (int r4 = 0; r4 < 8; r4++) {
            const ulonglong2 x4 = *(const ulonglong2*)&xs_t[k][r4 * 4];
            acc[r4 * 2]     = ffma2(x4.x, w2, acc[r4 * 2]);
            acc[r4 * 2 + 1] = ffma2(x4.y, w2, acc[r4 * 2 + 1]);
        }
    }

    float* p = part + (size_t)blockIdx.y * SQ * C + c;
#pragma unroll
    for (int i = 0; i < 16; i++) {
        const float2 v = unpack2(acc[i]);
        p[(size_t)(2 * i)     * C] = v.x;
        p[(size_t)(2 * i + 1) * C] = v.y;
    }
}

// ---------------------------------------------------------------------------
// Reduce qkv partials + bias -> g_qkv ; scatter new K/V rows into present tail
// ---------------------------------------------------------------------------
__global__ __launch_bounds__(256) void reduce_qkv_kernel(
    const float* __restrict__ b, float* __restrict__ dout)
{
    const int c = blockIdx.x * 256 + threadIdx.x;   // 0..3071
    const int r = blockIdx.y;
    float v = b[c];
#pragma unroll
    for (int kc = 0; kc < KCH; kc++)
        v += g_pqkv[((size_t)kc * SQ + r) * (3 * EMB) + c];
    g_qkv[r * 3 * EMB + c] = v;
    if (c >= EMB) {
        const int which = (c >= 2 * EMB) ? 1 : 0;   // 0=K, 1=V
        const int cc = c - EMB - which * EMB;
        const int h = cc / HD, d = cc % HD;
        dout[(size_t)SQ * EMB
             + ((size_t)which * NH + h) * (size_t)TOT * HD
             + (size_t)(PASTN + r) * HD + d] = v;
    }
}

// ---------------------------------------------------------------------------
// Attention: lane = query row, warp = one (head, split).
// cp.async double-buffered K/V tiles (16 keys). grid (NSPLITS, 4), 128 thr.
// Dynamic smem: per warp K[2][16][64] + V[2][16][64] -> 16KB, 64KB/CTA.
// ---------------------------------------------------------------------------
__global__ __launch_bounds__(128, 2) void attn_kernel(
    const float* __restrict__ past, float* __restrict__ dout)
{
    extern __shared__ float smem[];
    const int wid = threadIdx.x >> 5, lane = threadIdx.x & 31;
    const int sp = blockIdx.x;
    const int h  = blockIdx.y * 4 + wid;

    float* Kb = smem + wid * 2048;            // [2][16][64]
    float* Vb = smem + 8192 + wid * 2048;     // [2][16][64]
    const unsigned int KbA = (unsigned int)__cvta_generic_to_shared(Kb);
    const unsigned int VbA = (unsigned int)__cvta_generic_to_shared(Vb);

    const bool isnew = (sp == NSPLITS - 1);
    int t0, tend;
    if (isnew) { t0 = PASTN; tend = TOT; }
    else       { t0 = sp * PCHUNK; tend = min(t0 + PCHUNK, PASTN); }
    const int nt = (tend - t0) >> 4;          // 16-key tiles

    // q for row `lane`, pre-scaled by 1/sqrt(d) * log2(e)
    const float qc = 0.125f * 1.4426950408889634f;
    unsigned long long q2[32];
    {
        const float* qp = g_qkv + lane * 3 * EMB + h * HD;
#pragma unroll
        for (int i = 0; i < 16; i++) {
            const float4 v = *(const float4*)(qp + i * 4);
            q2[2 * i]     = pack2(v.x * qc, v.y * qc);
            q2[2 * i + 1] = pack2(v.z * qc, v.w * qc);
        }
    }

    unsigned long long o2[32];
#pragma unroll
    for (int i = 0; i < 32; i++) o2[i] = 0ull;
    float m = -1e30f, l = 0.f;

    float* presK = dout + SQ * EMB + (size_t)h * TOT * HD;
    float* presV = presK + (size_t)NH * TOT * HD;
    const float* srcK = isnew ? (presK + (size_t)t0 * HD)
                              : (past + ((size_t)h * PASTN + t0) * (size_t)HD);
    const float* srcV = isnew ? (presV + (size_t)t0 * HD)
                              : (past + ((size_t)(NH + h) * PASTN + t0) * (size_t)HD);

    // prefetch tile 0
    {
#pragma unroll
        for (int r = 0; r < 8; r++) {
            const int f4 = r * 32 + lane;
            cp16(KbA + (unsigned)f4 * 16, srcK + (size_t)f4 * 4);
            cp16(VbA + (unsigned)f4 * 16, srcV + (size_t)f4 * 4);
        }
        asm volatile("cp.async.commit_group;");
    }

    for (int i = 0; i < nt; i++) {
        const int buf = i & 1;
        if (i + 1 < nt) {                     // prefetch next tile
            const unsigned boff = (unsigned)((i + 1) & 1) * 4096u;
            const size_t gbase = (size_t)(i + 1) * 16 * HD;
#pragma unroll
            for (int r = 0; r < 8; r++) {
                const int f4 = r * 32 + lane;
                cp16(KbA + boff + (unsigned)f4 * 16, srcK + gbase + (size_t)f4 * 4);
                cp16(VbA + boff + (unsigned)f4 * 16, srcV + gbase + (size_t)f4 * 4);
            }
            asm volatile("cp.async.commit_group;");
            asm volatile("cp.async.wait_group 1;");
        } else {
            asm volatile("cp.async.wait_group 0;");
        }
        __syncwarp();

        const float* K = Kb + buf * 1024;
        const float* V = Vb + buf * 1024;
        const int tt = t0 + i * 16;

        // ---- copy-through to present (from smem) ----
        if (!isnew) {
#pragma unroll
            for (int r = 0; r < 8; r++) {
                const int f4 = r * 32 + lane;
                const float4 kv = *(const float4*)(K + f4 * 4);
                const float4 vv = *(const float4*)(V + f4 * 4);
                *(float4*)&presK[(size_t)tt * HD + (size_t)f4 * 4] = kv;
                *(float4*)&presV[(size_t)tt * HD + (size_t)f4 * 4] = vv;
            }
        }

        // ---- scores for 16 keys (broadcast LDS) ----
        float s[16];
#pragma unroll
        for (int kk = 0; kk < 16; kk++) {
            unsigned long long a0 = 0ull, a1 = 0ull;
            const float* Kr = K + kk * HD;
#pragma unroll
            for (int ii = 0; ii < 16; ii++) {
                const ulonglong2 k2 = *(const ulonglong2*)(Kr + ii * 4);
                a0 = ffma2(q2[2 * ii],     k2.x, a0);
                a1 = ffma2(q2[2 * ii + 1], k2.y, a1);
            }
            const float2 fa = unpack2(a0), fb = unpack2(a1);
            s[kk] = (fa.x + fa.y) + (fb.x + fb.y);
            if (isnew) {
                if (tt - PASTN + kk > lane) s[kk] = -1e30f;
            }
        }

        // ---- online softmax update ----
        float tm = s[0];
#pragma unroll
        for (int kk = 1; kk < 16; kk++) tm = fmaxf(tm, s[kk]);
        const float nm = fmaxf(m, tm);
        const float al = ex2(m - nm);
        m = nm;
        float ps = 0.f;
#pragma unroll
        for (int kk = 0; kk < 16; kk++) {
            s[kk] = ex2(s[kk] - nm);
            ps += s[kk];
        }
        l = l * al + ps;
        const unsigned long long al2 = pack2(al, al);
#pragma unroll
        for (int i2 = 0; i2 < 32; i2++) o2[i2] = mul2(o2[i2], al2);

        // ---- PV accumulate ----
#pragma unroll
        for (int kk = 0; kk < 16; kk++) {
            const unsigned long long p2 = pack2(s[kk], s[kk]);
            const float* Vr = V + kk * HD;
#pragma unroll
            for (int ii = 0; ii < 16; ii++) {
                const ulonglong2 v2 = *(const ulonglong2*)(Vr + ii * 4);
                o2[2 * ii]     = ffma2(p2, v2.x, o2[2 * ii]);
                o2[2 * ii + 1] = ffma2(p2, v2.y, o2[2 * ii + 1]);
            }
        }
    }

    // ---- epilogue: per-lane partial (m, l, o) ----
    const int pb = (h * NSPLITS + sp) * SQ + lane;
    float* pop = g_po + (size_t)pb * HD;
#pragma unroll
    for (int i = 0; i < 16; i++) {
        const float2 a = unpack2(o2[2 * i]);
        const float2 b = unpack2(o2[2 * i + 1]);
        float4 v; v.x = a.x; v.y = a.y; v.z = b.x; v.w = b.y;
        *(float4*)&pop[i * 4] = v;
    }
    g_pml[pb * 2]     = m;
    g_pml[pb * 2 + 1] = l;
}

// ---------------------------------------------------------------------------
// Combine split partials -> g_a. grid (NH, SQ), 256 threads:
// 4 split-groups x 64 dims, smem tree-reduce.
// ---------------------------------------------------------------------------
__global__ __launch_bounds__(256) void combine_kernel()
{
    const int h = blockIdx.x, j = blockIdx.y;
    const int d = threadIdx.x & 63, grp = threadIdx.x >> 6;
    __shared__ float sm[NSPLITS], sf[NSPLITS];
    __shared__ float sO[4][HD], sL[4];

    for (int i = threadIdx.x; i < NSPLITS; i += 256)
        sm[i] = g_pml[((h * NSPLITS + i) * SQ + j) * 2];
    __syncthreads();

    float g0 = -1e30f, g1 = -1e30f, g2 = -1e30f, g3 = -1e30f;
#pragma unroll 4
    for (int i = 0; i < NSPLITS; i += 4) {
        g0 = fmaxf(g0, sm[i]);     g1 = fmaxf(g1, sm[i + 1]);
        g2 = fmaxf(g2, sm[i + 2]); g3 = fmaxf(g3, sm[i + 3]);
    }
    const float gm = fmaxf(fmaxf(g0, g1), fmaxf(g2, g3));
    for (int i = threadIdx.x; i < NSPLITS; i += 256)
        sf[i] = ex2(sm[i] - gm);
    __syncthreads();

    float L = 0.f, o = 0.f;
    for (int i = grp; i < NSPLITS; i += 4) {
        const float f = sf[i];
        const int idx = (h * NSPLITS + i) * SQ + j;
        L = fmaf(g_pml[idx * 2 + 1], f, L);
        o = fmaf(f, g_po[(size_t)idx * HD + d], o);
    }
    sO[grp][d] = o;
    if (d == 0) sL[grp] = L;
    __syncthreads();
    if (grp == 0) {
        const float oo = (sO[0][d] + sO[1][d]) + (sO[2][d] + sO[3][d]);
        const float LL = (sL[0] + sL[1]) + (sL[2] + sL[3]);
        g_a[j * EMB + h * HD + d] = oo / LL;
    }
}

// ---------------------------------------------------------------------------
// Reduce proj partials + bias -> d_out[0 : 32*1024)
// ---------------------------------------------------------------------------
__global__ __launch_bounds__(256) void reduce_proj_kernel(
    const float* __restrict__ b, float* __restrict__ dout)
{
    const int c = blockIdx.x * 256 + threadIdx.x;   // 0..1023
    const int r = blockIdx.y;
    float v = b[c];
#pragma unroll
    for (int kc = 0; kc < KCH; kc++)
        v += g_pprj[((size_t)kc * SQ + r) * EMB + c];
    dout[r * EMB + c] = v;
}

// ---------------------------------------------------------------------------
extern "C" void kernel_launch(void* const* d_in, const int* in_sizes, int n_in,
                              void* d_out, int out_size)
{
    const float* x      = (const float*)d_in[0];
    const float* past   = (const float*)d_in[1];
    const float* w_attn = (const float*)d_in[2];
    const float* b_attn = (const float*)d_in[3];
    const float* w_proj = (const float*)d_in[4];
    const float* b_proj = (const float*)d_in[5];
    float* out = (float*)d_out;

    float* pqkv; cudaGetSymbolAddress((void**)&pqkv, g_pqkv);
    float* pprj; cudaGetSymbolAddress((void**)&pprj, g_pprj);
    float* ga;   cudaGetSymbolAddress((void**)&ga,   g_a);

    cudaFuncSetAttribute(attn_kernel,
                         cudaFuncAttributeMaxDynamicSharedMemorySize, 65536);

    gemm_part_kernel  <<<dim3(24, KCH), 128>>>(x, w_attn, pqkv, 3 * EMB);
    reduce_qkv_kernel <<<dim3(12, SQ),  256>>>(b_attn, out);
    attn_kernel       <<<dim3(NSPLITS, 4), 128, 65536>>>(past, out);
    combine_kernel    <<<dim3(NH, SQ),  256>>>();
    gemm_part_kernel  <<<dim3(8, KCH),  128>>>(ga, w_proj, pprj, EMB);
    reduce_proj_kernel<<<dim3(4, SQ),   256>>>(b_proj, out);
}